// round 1
// baseline (speedup 1.0000x reference)
#include <cuda_runtime.h>

// ExodusNeuron: per-(b,n) sequential scan over T time steps.
//   v_syn = alpha*v_syn + x*w ; v_mem = alpha*v_mem + v_syn
//   spk = (v_mem >= 1) ; v_mem -= spk
// x: (32, 2048, 512, 1) fp32 row-major -> idx = b*T*N + t*N + n
// Thread = one (b,n) sequence; warp loads are coalesced across n at each t.
// Double-buffered register prefetch of U steps hides DRAM latency despite
// only 512 warps chip-wide.

#define B_DIM 32
#define T_STEPS 2048
#define N_DIM 512
#define U 32
#define BLOCK 64

__global__ __launch_bounds__(BLOCK)
void exodus_kernel(const float* __restrict__ x,
                   const float* __restrict__ w,
                   float* __restrict__ out) {
    const int seq = blockIdx.x * BLOCK + threadIdx.x;   // 0..16383
    const int b = seq >> 9;          // /512
    const int n = seq & (N_DIM - 1); // %512

    const float weight = w[0];
    const float alpha  = 0.95122942450071400910f;  // exp(-1/20), rounds to f32

    const long base = (long)b * (T_STEPS * N_DIM) + n;
    const float* __restrict__ xp = x   + base;
    float*       __restrict__ op = out + base;

    float vs = 0.0f, vm = 0.0f;
    float buf[2][U];

    // Prime buffer 0
    #pragma unroll
    for (int u = 0; u < U; u++)
        buf[0][u] = __ldcs(xp + u * N_DIM);

    // Unroll by 2 so cur/nxt are compile-time constants -> buf stays in regs.
    #pragma unroll 2
    for (int t0 = 0; t0 < T_STEPS; t0 += U) {
        const int cur = (t0 / U) & 1;
        const int nxt = cur ^ 1;

        // Prefetch next tile (independent of scan state -> deep MLP)
        if (t0 + U < T_STEPS) {
            #pragma unroll
            for (int u = 0; u < U; u++)
                buf[nxt][u] = __ldcs(xp + (long)(t0 + U + u) * N_DIM);
        }

        // Consume current tile
        #pragma unroll
        for (int u = 0; u < U; u++) {
            const float xi = buf[cur][u] * weight;     // matches ref: x*w rounded first
            vs = fmaf(alpha, vs, xi);                  // ExpLeak
            vm = fmaf(alpha, vm, vs);                  // LIF integrate
            const float s = (vm >= 1.0f) ? 1.0f : 0.0f;
            vm -= s;                                   // membrane-subtract reset
            __stcs(op + (long)(t0 + u) * N_DIM, s);    // streaming store
        }
    }
}

extern "C" void kernel_launch(void* const* d_in, const int* in_sizes, int n_in,
                              void* d_out, int out_size) {
    const float* x = (const float*)d_in[0];
    const float* w = (const float*)d_in[1];
    float* out = (float*)d_out;

    const int total = B_DIM * N_DIM;          // 16384 sequences
    exodus_kernel<<<total / BLOCK, BLOCK>>>(x, w, out);
}

// round 2
// speedup vs baseline: 1.7382x; 1.7382x over previous
#include <cuda_runtime.h>
#include <cstdint>

// ExodusNeuron scan: v_syn = a*v_syn + x*w ; v_mem' = a*v_mem + v_syn ;
// spk = v_mem' >= 1 ; v_mem = spk ? v_mem'-1 : v_mem'   (bit-identical to vm'-spk)
//
// x: (32, 2048, 512, 1) fp32. Thread = one (b,n) sequence; 256 blocks x 64 thr.
// Input streamed via cp.async into a 3-stage smem ring (64 time-steps/stage):
// prefetch distance ~2 tiles (~1700+ cyc) >> DRAM latency, independent of
// register count. Consume via conflict-free LDS with 2-row lookahead.

#define T_STEPS 2048
#define N_DIM   512
#define BLOCK   64
#define U       64                    // time-steps per tile
#define NT      (T_STEPS / U)         // 32 tiles
#define STAGES  3
#define TILE_FLOATS (U * BLOCK)       // 4096 floats = 16 KB
#define TILE_BYTES  (TILE_FLOATS * 4)

__device__ __forceinline__ void cp_async16(uint32_t saddr, const void* gaddr) {
    asm volatile("cp.async.cg.shared.global [%0], [%1], 16;\n"
                 :: "r"(saddr), "l"(gaddr));
}
__device__ __forceinline__ void cp_commit() {
    asm volatile("cp.async.commit_group;\n" ::: "memory");
}

__global__ __launch_bounds__(BLOCK)
void exodus_kernel(const float* __restrict__ x,
                   const float* __restrict__ w,
                   float* __restrict__ out) {
    __shared__ float smem[STAGES * TILE_FLOATS];   // 48 KB exactly

    const int tid = threadIdx.x;
    const int b   = blockIdx.x >> 3;          // 32 batches
    const int n0  = (blockIdx.x & 7) * BLOCK; // 8 n-chunks of 64

    const float weight = w[0];
    const float alpha  = 0.95122942450071400910f;   // exp(-1/20) as f32

    const long gbase = (long)b * (T_STEPS * N_DIM) + n0;
    const float* __restrict__ xblk = x + gbase;
    float* __restrict__ oplane = out + gbase + tid;

    const uint32_t sbase = (uint32_t)__cvta_generic_to_shared(smem);

    // Loader mapping: each row (time-step) = 64 floats = 256 B = 16 x 16 B.
    // laneCol = tid & 15 covers a row; rowBase = tid >> 4 staggers 4 rows.
    const int laneCol = tid & 15;
    const int rowBase = tid >> 4;

    auto issue_tile = [&](int tt) {
        const int stage = tt % STAGES;
        uint32_t s0 = sbase + stage * TILE_BYTES + rowBase * 256 + laneCol * 16;
        const float* g0 = xblk + (long)(tt * U + rowBase) * N_DIM + laneCol * 4;
        #pragma unroll
        for (int i = 0; i < U / 4; i++)
            cp_async16(s0 + i * 4 * 256, g0 + (long)i * 4 * N_DIM);
        cp_commit();
    };

    // Prologue: 2 tiles in flight
    issue_tile(0);
    issue_tile(1);

    float vs = 0.0f, vm = 0.0f;

    for (int tt = 0; tt < NT; tt++) {
        __syncthreads();   // all threads done consuming the stage we overwrite
        if (tt + 2 < NT) issue_tile(tt + 2);

        // Wait until tile tt's group is complete (pending <= issued - (tt+1))
        if (tt + 3 <= NT)      asm volatile("cp.async.wait_group 2;\n" ::: "memory");
        else if (tt + 2 == NT) asm volatile("cp.async.wait_group 1;\n" ::: "memory");
        else                   asm volatile("cp.async.wait_group 0;\n" ::: "memory");
        __syncthreads();   // cross-thread visibility of the async copies

        const float* __restrict__ srow = smem + (tt % STAGES) * TILE_FLOATS + tid;
        float xv0 = srow[0];
        float xv1 = srow[BLOCK];

        #pragma unroll
        for (int r = 0; r < U; r++) {
            float xn = (r + 2 < U) ? srow[(r + 2) * BLOCK] : 0.0f;  // LDS 2 ahead
            const float xi  = xv0 * weight;          // x*w rounded first (as ref)
            vs = fmaf(alpha, vs, xi);                // ExpLeak
            const float vmp = fmaf(alpha, vm, vs);   // LIF integrate
            const bool  spk = (vmp >= 1.0f);
            const float vmr = vmp - 1.0f;            // parallel with compare
            vm = spk ? vmr : vmp;                    // FSEL, 12-cyc chain total
            __stcs(oplane + (long)(tt * U + r) * N_DIM, spk ? 1.0f : 0.0f);
            xv0 = xv1; xv1 = xn;
        }
    }
}

extern "C" void kernel_launch(void* const* d_in, const int* in_sizes, int n_in,
                              void* d_out, int out_size) {
    const float* x = (const float*)d_in[0];
    const float* w = (const float*)d_in[1];
    float* out = (float*)d_out;

    exodus_kernel<<<256, BLOCK>>>(x, w, out);   // 256 blocks x 64 threads = 16384 seqs
}